// round 6
// baseline (speedup 1.0000x reference)
#include <cuda_runtime.h>

#define BATCH       32768
#define NUM_CLASSES 1000
#define FEAT_DIM    128

#define S1_BLOCKS   2048
#define S1_THREADS  256
#define WARPS_PER_BLOCK (S1_THREADS / 32)            // 8
#define TOTAL_WARPS (S1_BLOCKS * WARPS_PER_BLOCK)    // 16384
#define ROWS_PER_WARP (BATCH / TOTAL_WARPS)          // 2

__device__ float        g_partial[S1_BLOCKS];
__device__ unsigned int g_count = 0;

__global__ void __launch_bounds__(S1_THREADS)
center_loss_fused(const float* __restrict__ y,
                  const int* __restrict__ labels,
                  const float* __restrict__ centers,
                  const float* __restrict__ loss_weight,
                  float* __restrict__ out)
{
    const int lane   = threadIdx.x & 31;
    const int warpId = threadIdx.x >> 5;
    const int gwarp  = blockIdx.x * WARPS_PER_BLOCK + warpId;

    const float4* __restrict__ y4 = (const float4*)y;
    const float4* __restrict__ c4 = (const float4*)centers;

    float acc = 0.0f;

    #pragma unroll
    for (int k = 0; k < ROWS_PER_WARP; k++) {
        const int row = gwarp + k * TOTAL_WARPS;
        const int cls = labels[row];                         // warp-uniform broadcast
        float4 yv = y4[row * (FEAT_DIM / 4) + lane];         // plain load: L2-resident
        float4 cv = __ldg(&c4[cls * (FEAT_DIM / 4) + lane]); // L2-resident table

        float s;
        s  = yv.x * yv.x + yv.y * yv.y + yv.z * yv.z + yv.w * yv.w;
        s += cv.x * cv.x + cv.y * cv.y + cv.z * cv.z + cv.w * cv.w;
        s -= 2.0f * (yv.x * cv.x + yv.y * cv.y + yv.z * cv.z + yv.w * cv.w);
        acc += s;
    }

    // ---- warp reduce ----
    #pragma unroll
    for (int off = 16; off > 0; off >>= 1)
        acc += __shfl_xor_sync(0xFFFFFFFFu, acc, off);

    // ---- block reduce ----
    __shared__ float smem[WARPS_PER_BLOCK];
    if (lane == 0) smem[warpId] = acc;
    __syncthreads();

    __shared__ bool isLast;
    if (threadIdx.x == 0) {
        float t = 0.0f;
        #pragma unroll
        for (int i = 0; i < WARPS_PER_BLOCK; i++) t += smem[i];
        g_partial[blockIdx.x] = t;
        __threadfence();
        unsigned int prev = atomicAdd(&g_count, 1u);
        isLast = (prev == (unsigned int)(gridDim.x - 1));
    }
    __syncthreads();

    // ---- last block: deterministic final reduce over 2048 partials ----
    if (isLast) {
        __shared__ float fin[S1_THREADS];
        float t = 0.0f;
        #pragma unroll
        for (int i = 0; i < S1_BLOCKS / S1_THREADS; i++)
            t += g_partial[threadIdx.x + i * S1_THREADS];
        fin[threadIdx.x] = t;
        __syncthreads();

        for (int off = S1_THREADS / 2; off > 0; off >>= 1) {
            if (threadIdx.x < off) fin[threadIdx.x] += fin[threadIdx.x + off];
            __syncthreads();
        }

        if (threadIdx.x == 0) {
            // masked-matrix zeros clip to 1e-12: + B*(C-1)*1e-12, then /B
            float clip_term = (float)((double)BATCH * (double)(NUM_CLASSES - 1) * 1e-12);
            float total = fin[0] + clip_term;
            out[0] = (total / (float)BATCH) * loss_weight[0];
            g_count = 0;  // reset for next graph replay
        }
    }
}

extern "C" void kernel_launch(void* const* d_in, const int* in_sizes, int n_in,
                              void* d_out, int out_size)
{
    // Identify inputs by element count (all distinct):
    //   y: 4194304, centers: 128000, labels: 32768, loss_weight: 1
    const float* y       = nullptr;
    const int*   labels  = nullptr;
    const float* centers = nullptr;
    const float* lw      = nullptr;

    for (int i = 0; i < n_in; i++) {
        switch (in_sizes[i]) {
            case BATCH * FEAT_DIM:       y       = (const float*)d_in[i]; break;
            case NUM_CLASSES * FEAT_DIM: centers = (const float*)d_in[i]; break;
            case BATCH:                  labels  = (const int*)d_in[i];   break;
            case 1:                      lw      = (const float*)d_in[i]; break;
            default: break;
        }
    }

    center_loss_fused<<<S1_BLOCKS, S1_THREADS>>>(y, labels, centers, lw, (float*)d_out);
}

// round 7
// speedup vs baseline: 1.2694x; 1.2694x over previous
#include <cuda_runtime.h>

#define BATCH       32768
#define NUM_CLASSES 1000
#define FEAT_DIM    128

#define S1_BLOCKS   1024
#define S1_THREADS  256
#define WARPS_PER_BLOCK (S1_THREADS / 32)            // 8
#define TOTAL_WARPS (S1_BLOCKS * WARPS_PER_BLOCK)    // 8192
#define ROWS_PER_WARP (BATCH / TOTAL_WARPS)          // 4

__device__ float        g_partial[S1_BLOCKS];
__device__ unsigned int g_count = 0;

__global__ void __launch_bounds__(S1_THREADS)
center_loss_fused(const float* __restrict__ y,
                  const int* __restrict__ labels,
                  const float* __restrict__ centers,
                  const float* __restrict__ loss_weight,
                  float* __restrict__ out)
{
    const int lane   = threadIdx.x & 31;
    const int warpId = threadIdx.x >> 5;
    const int gwarp  = blockIdx.x * WARPS_PER_BLOCK + warpId;

    const float4* __restrict__ y4 = (const float4*)y;
    const float4* __restrict__ c4 = (const float4*)centers;

    // ---- per-thread elementwise accumulation (no per-row reduce/clip) ----
    float acc = 0.0f;

    #pragma unroll
    for (int k = 0; k < ROWS_PER_WARP; k++) {
        const int row = gwarp + k * TOTAL_WARPS;
        const int cls = __ldg(&labels[row]);                 // warp-uniform broadcast
        float4 yv = y4[row * (FEAT_DIM / 4) + lane];         // plain load: L2-resident
        float4 cv = __ldg(&c4[cls * (FEAT_DIM / 4) + lane]); // hot table, L1/L2

        acc += yv.x * yv.x + yv.y * yv.y + yv.z * yv.z + yv.w * yv.w;
        acc += cv.x * cv.x + cv.y * cv.y + cv.z * cv.z + cv.w * cv.w;
        acc -= 2.0f * (yv.x * cv.x + yv.y * cv.y + yv.z * cv.z + yv.w * cv.w);
    }

    // ---- warp reduce ----
    #pragma unroll
    for (int off = 16; off > 0; off >>= 1)
        acc += __shfl_xor_sync(0xFFFFFFFFu, acc, off);

    // ---- block reduce ----
    __shared__ float smem[WARPS_PER_BLOCK];
    if (lane == 0) smem[warpId] = acc;
    __syncthreads();

    __shared__ bool isLast;
    if (threadIdx.x == 0) {
        float t = 0.0f;
        #pragma unroll
        for (int i = 0; i < WARPS_PER_BLOCK; i++) t += smem[i];
        g_partial[blockIdx.x] = t;
        __threadfence();
        unsigned int prev = atomicAdd(&g_count, 1u);
        isLast = (prev == (unsigned int)(gridDim.x - 1));
    }
    __syncthreads();

    // ---- last block: deterministic final reduce over 1024 partials ----
    if (isLast) {
        __shared__ float fin[S1_THREADS];
        float t = 0.0f;
        #pragma unroll
        for (int i = 0; i < S1_BLOCKS / S1_THREADS; i++)
            t += g_partial[threadIdx.x + i * S1_THREADS];
        fin[threadIdx.x] = t;
        __syncthreads();

        for (int off = S1_THREADS / 2; off > 0; off >>= 1) {
            if (threadIdx.x < off) fin[threadIdx.x] += fin[threadIdx.x + off];
            __syncthreads();
        }

        if (threadIdx.x == 0) {
            // masked-matrix zeros clip to 1e-12: + B*(C-1)*1e-12, then /B
            float clip_term = (float)((double)BATCH * (double)(NUM_CLASSES - 1) * 1e-12);
            float total = fin[0] + clip_term;
            out[0] = (total / (float)BATCH) * loss_weight[0];
            g_count = 0;  // reset for next graph replay
        }
    }
}

extern "C" void kernel_launch(void* const* d_in, const int* in_sizes, int n_in,
                              void* d_out, int out_size)
{
    // Identify inputs by element count (all distinct):
    //   y: 4194304, centers: 128000, labels: 32768, loss_weight: 1
    const float* y       = nullptr;
    const int*   labels  = nullptr;
    const float* centers = nullptr;
    const float* lw      = nullptr;

    for (int i = 0; i < n_in; i++) {
        switch (in_sizes[i]) {
            case BATCH * FEAT_DIM:       y       = (const float*)d_in[i]; break;
            case NUM_CLASSES * FEAT_DIM: centers = (const float*)d_in[i]; break;
            case BATCH:                  labels  = (const int*)d_in[i];   break;
            case 1:                      lw      = (const float*)d_in[i]; break;
            default: break;
        }
    }

    center_loss_fused<<<S1_BLOCKS, S1_THREADS>>>(y, labels, centers, lw, (float*)d_out);
}